// round 1
// baseline (speedup 1.0000x reference)
#include <cuda_runtime.h>
#include <math.h>

#define T_DIM 2048
#define N_DIM 2
#define C_DIM 1024
#define H_DIM 16
#define DH 64
#define M_ROWS (T_DIM * N_DIM)   // 4096
#define WINDOW 128

// Scratch (static device allocation — allowed; cudaMalloc is not)
__device__ float g_qp[M_ROWS * C_DIM];
__device__ float g_kp[M_ROWS * C_DIM];
__device__ float g_vp[M_ROWS * C_DIM];
__device__ float g_ao[M_ROWS * C_DIM];

// ---------------------------------------------------------------------------
// C[m][n] = sum_k A[m*K+k] * B[n*K+k] + bias[n]
// A: MxK row-major, B: NxK row-major (i.e. computes A @ B^T + bias)
// M, N multiples of 64; K multiple of 16.
// ---------------------------------------------------------------------------
__global__ __launch_bounds__(256) void sgemm_bias_kernel(
    const float* __restrict__ A, const float* __restrict__ B,
    const float* __restrict__ bias, float* __restrict__ C,
    int M, int N, int K)
{
    __shared__ float As[16][64];   // [k][m]
    __shared__ float Bs[16][64];   // [k][n]
    const int tx = threadIdx.x, ty = threadIdx.y;
    const int tid = ty * 16 + tx;
    const int m0 = blockIdx.y * 64, n0 = blockIdx.x * 64;

    float acc[4][4] = {};
    const int lr  = tid >> 2;        // 0..63 tile row
    const int lk4 = (tid & 3) * 4;   // 0,4,8,12 k offset

    for (int k0 = 0; k0 < K; k0 += 16) {
        float4 a4 = *(const float4*)&A[(size_t)(m0 + lr) * K + k0 + lk4];
        float4 b4 = *(const float4*)&B[(size_t)(n0 + lr) * K + k0 + lk4];
        As[lk4 + 0][lr] = a4.x; As[lk4 + 1][lr] = a4.y;
        As[lk4 + 2][lr] = a4.z; As[lk4 + 3][lr] = a4.w;
        Bs[lk4 + 0][lr] = b4.x; Bs[lk4 + 1][lr] = b4.y;
        Bs[lk4 + 2][lr] = b4.z; Bs[lk4 + 3][lr] = b4.w;
        __syncthreads();
        #pragma unroll
        for (int kk = 0; kk < 16; kk++) {
            float4 av = *(const float4*)&As[kk][ty * 4];
            float4 bv = *(const float4*)&Bs[kk][tx * 4];
            float a[4] = {av.x, av.y, av.z, av.w};
            float b[4] = {bv.x, bv.y, bv.z, bv.w};
            #pragma unroll
            for (int i = 0; i < 4; i++)
                #pragma unroll
                for (int j = 0; j < 4; j++)
                    acc[i][j] += a[i] * b[j];
        }
        __syncthreads();
    }

    #pragma unroll
    for (int i = 0; i < 4; i++) {
        const int m = m0 + ty * 4 + i;
        const int n = n0 + tx * 4;
        float4 bv = *(const float4*)&bias[n];
        float4 ov = {acc[i][0] + bv.x, acc[i][1] + bv.y,
                     acc[i][2] + bv.z, acc[i][3] + bv.w};
        *(float4*)&C[(size_t)m * N + n] = ov;
    }
}

// ---------------------------------------------------------------------------
// Flash-attention style masked attention, fp32, Bq=Bk=64.
// q/k/v projected tensors in (T, N, C) layout, C = H*DH.
// Mask: attend iff |i-j| <= WINDOW  OR  j < key_length[n].
// Dead 64-key blocks (neither condition reachable) are skipped entirely.
// ---------------------------------------------------------------------------
__global__ __launch_bounds__(256) void attn_kernel(
    const float* __restrict__ qp, const float* __restrict__ kp,
    const float* __restrict__ vp, float* __restrict__ ao,
    const int* __restrict__ key_length)
{
    extern __shared__ float sm[];
    float* Qs    = sm;               // [d][row]   64*64
    float* Ks    = Qs + 64 * 64;     // [d][col]   64*64
    float* Vs    = Ks + 64 * 64;     // [key][d]   64*64
    float* Ss    = Vs + 64 * 64;     // [row][66]  64*66 (padded)
    float* row_m = Ss + 64 * 66;     // 64
    float* row_l = row_m + 64;       // 64
    float* row_c = row_l + 64;       // 64

    const int tx = threadIdx.x, ty = threadIdx.y;
    const int tid = ty * 16 + tx;
    const int q0 = blockIdx.x * 64;
    const int h  = blockIdx.y;
    const int n  = blockIdx.z;
    const int kl = key_length[n];
    const float scale = 0.125f;   // 1/sqrt(64)

    // --- load Q tile transposed: Qs[d][row] ---
    {
        const int r  = tid >> 2;
        const int dq = (tid & 3) * 16;
        const float* src = &qp[((size_t)(q0 + r) * N_DIM + n) * C_DIM + h * DH + dq];
        #pragma unroll
        for (int u = 0; u < 16; u += 4) {
            float4 v4 = *(const float4*)&src[u];
            Qs[(dq + u + 0) * 64 + r] = v4.x;
            Qs[(dq + u + 1) * 64 + r] = v4.y;
            Qs[(dq + u + 2) * 64 + r] = v4.z;
            Qs[(dq + u + 3) * 64 + r] = v4.w;
        }
    }
    if (tid < 64) { row_m[tid] = -1e30f; row_l[tid] = 0.0f; }

    float o[4][4] = {};

    for (int kb = 0; kb < T_DIM / 64; kb++) {
        const int k0 = kb * 64;
        // block-level mask skip (uniform across block — no divergence)
        const bool include = (k0 < kl) ||
                             (k0 <= q0 + 63 + WINDOW && k0 + 63 >= q0 - WINDOW);
        if (!include) continue;

        // --- load K (transposed) + V (natural) ---
        {
            const int r  = tid >> 2;
            const int dq = (tid & 3) * 16;
            const float* ksrc = &kp[((size_t)(k0 + r) * N_DIM + n) * C_DIM + h * DH + dq];
            const float* vsrc = &vp[((size_t)(k0 + r) * N_DIM + n) * C_DIM + h * DH + dq];
            #pragma unroll
            for (int u = 0; u < 16; u += 4) {
                float4 kv = *(const float4*)&ksrc[u];
                Ks[(dq + u + 0) * 64 + r] = kv.x;
                Ks[(dq + u + 1) * 64 + r] = kv.y;
                Ks[(dq + u + 2) * 64 + r] = kv.z;
                Ks[(dq + u + 3) * 64 + r] = kv.w;
                float4 vv = *(const float4*)&vsrc[u];
                *(float4*)&Vs[r * 64 + dq + u] = vv;
            }
        }
        __syncthreads();

        // --- S = Q K^T (4x4 per thread) ---
        float s[4][4] = {};
        #pragma unroll 4
        for (int d = 0; d < 64; d++) {
            float4 av = *(const float4*)&Qs[d * 64 + ty * 4];
            float4 bv = *(const float4*)&Ks[d * 64 + tx * 4];
            float a[4] = {av.x, av.y, av.z, av.w};
            float b[4] = {bv.x, bv.y, bv.z, bv.w};
            #pragma unroll
            for (int i = 0; i < 4; i++)
                #pragma unroll
                for (int j = 0; j < 4; j++)
                    s[i][j] += a[i] * b[j];
        }
        // mask + scale, write scores to shared
        #pragma unroll
        for (int i = 0; i < 4; i++) {
            const int gi = q0 + ty * 4 + i;
            #pragma unroll
            for (int j = 0; j < 4; j++) {
                const int gj = k0 + tx * 4 + j;
                const bool att = (abs(gi - gj) <= WINDOW) || (gj < kl);
                Ss[(ty * 4 + i) * 66 + tx * 4 + j] = att ? s[i][j] * scale : -1e9f;
            }
        }
        __syncthreads();

        // --- online softmax: 4 threads per row, 16 cols each ---
        {
            const int r  = tid >> 2;
            const int qd = tid & 3;
            float* srow = &Ss[r * 66 + qd * 16];
            float mx = -1e30f;
            #pragma unroll
            for (int c = 0; c < 16; c++) mx = fmaxf(mx, srow[c]);
            mx = fmaxf(mx, __shfl_xor_sync(0xffffffffu, mx, 1));
            mx = fmaxf(mx, __shfl_xor_sync(0xffffffffu, mx, 2));
            const float m_old = row_m[r];
            const float m_new = fmaxf(m_old, mx);
            const float corr  = __expf(m_old - m_new);
            float sum = 0.0f;
            #pragma unroll
            for (int c = 0; c < 16; c++) {
                const float p = __expf(srow[c] - m_new);
                srow[c] = p;
                sum += p;
            }
            sum += __shfl_xor_sync(0xffffffffu, sum, 1);
            sum += __shfl_xor_sync(0xffffffffu, sum, 2);
            if (qd == 0) {
                row_l[r] = row_l[r] * corr + sum;
                row_m[r] = m_new;
                row_c[r] = corr;
            }
        }
        __syncthreads();

        // --- O = O*corr + P V ---
        #pragma unroll
        for (int i = 0; i < 4; i++) {
            const float corr = row_c[ty * 4 + i];
            #pragma unroll
            for (int j = 0; j < 4; j++) o[i][j] *= corr;
        }
        #pragma unroll 4
        for (int kk = 0; kk < 64; kk++) {
            float4 vv = *(const float4*)&Vs[kk * 64 + tx * 4];
            #pragma unroll
            for (int i = 0; i < 4; i++) {
                const float p = Ss[(ty * 4 + i) * 66 + kk];
                o[i][0] += p * vv.x;
                o[i][1] += p * vv.y;
                o[i][2] += p * vv.z;
                o[i][3] += p * vv.w;
            }
        }
        __syncthreads();
    }

    // --- normalize + write out ---
    #pragma unroll
    for (int i = 0; i < 4; i++) {
        const int r = ty * 4 + i;
        const float inv = 1.0f / row_l[r];
        float* dst = &ao[((size_t)(q0 + r) * N_DIM + n) * C_DIM + h * DH + tx * 4];
        float4 ov = {o[i][0] * inv, o[i][1] * inv, o[i][2] * inv, o[i][3] * inv};
        *(float4*)dst = ov;
    }
}

// ---------------------------------------------------------------------------
extern "C" void kernel_launch(void* const* d_in, const int* in_sizes, int n_in,
                              void* d_out, int out_size)
{
    (void)in_sizes; (void)n_in; (void)out_size;
    const float* q  = (const float*)d_in[0];
    const float* k  = (const float*)d_in[1];
    const float* v  = (const float*)d_in[2];
    const float* Wq = (const float*)d_in[3];
    const float* bq = (const float*)d_in[4];
    const float* Wk = (const float*)d_in[5];
    const float* bk = (const float*)d_in[6];
    const float* Wv = (const float*)d_in[7];
    const float* bv = (const float*)d_in[8];
    const float* Wo = (const float*)d_in[9];
    const float* bo = (const float*)d_in[10];
    const int* key_length = (const int*)d_in[11];
    float* out = (float*)d_out;

    float *qp, *kp, *vp, *aop;
    cudaGetSymbolAddress((void**)&qp,  g_qp);
    cudaGetSymbolAddress((void**)&kp,  g_kp);
    cudaGetSymbolAddress((void**)&vp,  g_vp);
    cudaGetSymbolAddress((void**)&aop, g_ao);

    const dim3 gBlk(16, 16);
    const dim3 gGrid(C_DIM / 64, M_ROWS / 64);  // (16, 64)

    // input projections
    sgemm_bias_kernel<<<gGrid, gBlk>>>(q, Wq, bq, qp, M_ROWS, C_DIM, C_DIM);
    sgemm_bias_kernel<<<gGrid, gBlk>>>(k, Wk, bk, kp, M_ROWS, C_DIM, C_DIM);
    sgemm_bias_kernel<<<gGrid, gBlk>>>(v, Wv, bv, vp, M_ROWS, C_DIM, C_DIM);

    // attention
    const int smem_bytes = (3 * 64 * 64 + 64 * 66 + 3 * 64) * sizeof(float); // 66816
    cudaFuncSetAttribute(attn_kernel,
                         cudaFuncAttributeMaxDynamicSharedMemorySize, smem_bytes);
    attn_kernel<<<dim3(T_DIM / 64, H_DIM, N_DIM), gBlk, smem_bytes>>>(
        qp, kp, vp, aop, key_length);

    // output projection
    sgemm_bias_kernel<<<gGrid, gBlk>>>(aop, Wo, bo, out, M_ROWS, C_DIM, C_DIM);
}

// round 8
// speedup vs baseline: 3.0033x; 3.0033x over previous
#include <cuda_runtime.h>
#include <math.h>
#include <stdint.h>

#define T_DIM 2048
#define N_DIM 2
#define C_DIM 1024
#define H_DIM 16
#define DH 64
#define M_ROWS (T_DIM * N_DIM)   // 4096
#define WINDOW 128

#define GK 1024
#define GN 1024
#define BK 32
#define NUM_CHUNKS (GK / BK)     // 32
#define SM_STRIDE 36             // 32 + 4 pad (floats)
#define STAGE_F (128 * SM_STRIDE)            // floats per matrix tile
#define GEMM_SMEM (2 * 2 * STAGE_F * 4)      // 2 stages x (A+B) = 73728 B

// Scratch (static device allocation — allowed; cudaMalloc is not)
__device__ float g_qp[M_ROWS * C_DIM];
__device__ float g_kp[M_ROWS * C_DIM];
__device__ float g_vp[M_ROWS * C_DIM];
__device__ float g_ao[M_ROWS * C_DIM];

// ---------------------------------------------------------------------------
__device__ __forceinline__ float to_tf32(float x) {
    float y;
    asm("cvt.rna.tf32.f32 %0, %1;" : "=f"(y) : "f"(x));
    return y;
}
__device__ __forceinline__ float4 to_tf32x4(float4 v) {
    return make_float4(to_tf32(v.x), to_tf32(v.y), to_tf32(v.z), to_tf32(v.w));
}

__device__ __forceinline__ void mma_tf32(float* c, const uint32_t* a,
                                         uint32_t b0, uint32_t b1) {
    asm volatile(
        "mma.sync.aligned.m16n8k8.row.col.f32.tf32.tf32.f32 "
        "{%0,%1,%2,%3}, {%4,%5,%6,%7}, {%8,%9}, {%0,%1,%2,%3};"
        : "+f"(c[0]), "+f"(c[1]), "+f"(c[2]), "+f"(c[3])
        : "r"(a[0]), "r"(a[1]), "r"(a[2]), "r"(a[3]), "r"(b0), "r"(b1));
}

// ---------------------------------------------------------------------------
// mma.sync tf32 GEMM: C[m][n] = sum_k A[m][k]*B[n][k] + bias[n]
// A: M x 1024 row-major, B: 1024 x 1024 row-major (computes A @ B^T + bias).
// CTA tile 128x128, BK=32, 8 warps (4m x 2n), warp tile 32x64.
// ---------------------------------------------------------------------------
__global__ __launch_bounds__(256) void gemm_tf32_kernel(
    const float* __restrict__ A, const float* __restrict__ B,
    const float* __restrict__ bias, float* __restrict__ C)
{
    extern __shared__ float sm[];
    const int tid  = threadIdx.x;
    const int wid  = tid >> 5;
    const int lane = tid & 31;
    const int g    = lane >> 2;     // group id 0..7
    const int t    = lane & 3;      // thread-in-group 0..3
    const int warpM = (wid & 3) * 32;
    const int warpN = (wid >> 2) * 64;
    const int m0 = blockIdx.y * 128;
    const int n0 = blockIdx.x * 128;

    const int lr  = tid >> 3;         // 0..31 row within pass
    const int lc4 = (tid & 7) * 4;    // float4 col offset

    float acc[2][8][4] = {};

    // --- load chunk 0 into stage 0 ---
    {
        float* As = sm;
        float* Bs = sm + STAGE_F;
        #pragma unroll
        for (int it = 0; it < 4; it++) {
            const int row = it * 32 + lr;
            float4 a4 = *(const float4*)&A[(size_t)(m0 + row) * GK + lc4];
            float4 b4 = *(const float4*)&B[(size_t)(n0 + row) * GK + lc4];
            *(float4*)&As[row * SM_STRIDE + lc4] = to_tf32x4(a4);
            *(float4*)&Bs[row * SM_STRIDE + lc4] = to_tf32x4(b4);
        }
    }
    __syncthreads();

    int s = 0;
    for (int c = 0; c < NUM_CHUNKS; c++) {
        const bool more = (c + 1 < NUM_CHUNKS);
        float4 pa[4], pb[4];
        if (more) {
            const int kc = (c + 1) * BK;
            #pragma unroll
            for (int it = 0; it < 4; it++) {
                const int row = it * 32 + lr;
                pa[it] = *(const float4*)&A[(size_t)(m0 + row) * GK + kc + lc4];
                pb[it] = *(const float4*)&B[(size_t)(n0 + row) * GK + kc + lc4];
            }
        }

        // --- compute on stage s ---
        {
            const uint32_t* Asu = (const uint32_t*)(sm + 2 * s * STAGE_F);
            const uint32_t* Bsu = Asu + STAGE_F;
            #pragma unroll
            for (int ks = 0; ks < 4; ks++) {
                const int k0 = ks * 8 + t;
                uint32_t af[2][4];
                #pragma unroll
                for (int mt = 0; mt < 2; mt++) {
                    const int rb = warpM + mt * 16 + g;
                    af[mt][0] = Asu[rb * SM_STRIDE + k0];
                    af[mt][1] = Asu[(rb + 8) * SM_STRIDE + k0];
                    af[mt][2] = Asu[rb * SM_STRIDE + k0 + 4];
                    af[mt][3] = Asu[(rb + 8) * SM_STRIDE + k0 + 4];
                }
                #pragma unroll
                for (int nt = 0; nt < 8; nt++) {
                    const int cb = warpN + nt * 8 + g;
                    const uint32_t b0 = Bsu[cb * SM_STRIDE + k0];
                    const uint32_t b1 = Bsu[cb * SM_STRIDE + k0 + 4];
                    mma_tf32(acc[0][nt], af[0], b0, b1);
                    mma_tf32(acc[1][nt], af[1], b0, b1);
                }
            }
        }

        if (more) {
            __syncthreads();   // everyone done reading stage s^1 (from iter c-1)
            float* As = sm + 2 * (s ^ 1) * STAGE_F;
            float* Bs = As + STAGE_F;
            #pragma unroll
            for (int it = 0; it < 4; it++) {
                const int row = it * 32 + lr;
                *(float4*)&As[row * SM_STRIDE + lc4] = to_tf32x4(pa[it]);
                *(float4*)&Bs[row * SM_STRIDE + lc4] = to_tf32x4(pb[it]);
            }
            __syncthreads();
            s ^= 1;
        }
    }

    // --- epilogue: bias + store ---
    #pragma unroll
    for (int mt = 0; mt < 2; mt++) {
        #pragma unroll
        for (int nt = 0; nt < 8; nt++) {
            const int row = m0 + warpM + mt * 16 + g;
            const int col = n0 + warpN + nt * 8 + 2 * t;
            float2 bb = *(const float2*)&bias[col];
            float2 v0 = {acc[mt][nt][0] + bb.x, acc[mt][nt][1] + bb.y};
            float2 v1 = {acc[mt][nt][2] + bb.x, acc[mt][nt][3] + bb.y};
            *(float2*)&C[(size_t)row * GN + col] = v0;
            *(float2*)&C[(size_t)(row + 8) * GN + col] = v1;
        }
    }
}

// ---------------------------------------------------------------------------
// Tensor-core flash attention, Bq=Bk=64. QK^T and PV on mma.sync tf32;
// masking + online softmax in shared memory (structure unchanged from the
// validated fp32 version).
// 8 warps as 4(M) x 2(N): warp strip = 16 query rows x 32 cols.
// Qs [row][68] natural, Ks [key][68] natural, Vs [d][68] transposed,
// Ss [row][66] scores/probs.
// ---------------------------------------------------------------------------
#define AQ 68
#define SSW 66
#define ATTN_SMEM ((3 * 64 * AQ + 64 * SSW + 3 * 64) * 4)   // 69888 B

__global__ __launch_bounds__(256) void attn_kernel(
    const float* __restrict__ qp, const float* __restrict__ kp,
    const float* __restrict__ vp, float* __restrict__ ao,
    const int* __restrict__ key_length)
{
    extern __shared__ float sm[];
    float* Qs    = sm;                    // [row][AQ]
    float* Ks    = Qs + 64 * AQ;          // [key][AQ]
    float* Vs    = Ks + 64 * AQ;          // [d][AQ]   (transposed)
    float* Ss    = Vs + 64 * AQ;          // [row][SSW]
    float* row_m = Ss + 64 * SSW;         // 64
    float* row_l = row_m + 64;            // 64
    float* row_c = row_l + 64;            // 64

    const int tid  = threadIdx.x;
    const int wid  = tid >> 5;
    const int lane = tid & 31;
    const int g    = lane >> 2;           // 0..7
    const int t    = lane & 3;            // 0..3
    const int warpM = (wid & 3) * 16;
    const int warpN = (wid >> 2) * 32;

    const int q0 = blockIdx.x * 64;
    const int h  = blockIdx.y;
    const int n  = blockIdx.z;
    const int kl = key_length[n];
    const float scale = 0.125f;   // 1/sqrt(64)

    const int r  = tid >> 2;              // 0..63
    const int dq = (tid & 3) * 16;

    // --- load Q natural, tf32-rounded ---
    {
        const float* src = &qp[((size_t)(q0 + r) * N_DIM + n) * C_DIM + h * DH + dq];
        #pragma unroll
        for (int u = 0; u < 16; u += 4)
            *(float4*)&Qs[r * AQ + dq + u] = to_tf32x4(*(const float4*)&src[u]);
    }
    if (tid < 64) { row_m[tid] = -1e30f; row_l[tid] = 0.0f; }

    float o[4][4] = {};   // [nt][c-frag], O accumulator fragments

    for (int kb = 0; kb < T_DIM / 64; kb++) {
        const int k0b = kb * 64;
        const bool include = (k0b < kl) ||
                             (k0b <= q0 + 63 + WINDOW && k0b + 63 >= q0 - WINDOW);
        if (!include) continue;

        // --- load K natural + V transposed, tf32-rounded ---
        {
            const float* ksrc = &kp[((size_t)(k0b + r) * N_DIM + n) * C_DIM + h * DH + dq];
            const float* vsrc = &vp[((size_t)(k0b + r) * N_DIM + n) * C_DIM + h * DH + dq];
            #pragma unroll
            for (int u = 0; u < 16; u += 4) {
                *(float4*)&Ks[r * AQ + dq + u] = to_tf32x4(*(const float4*)&ksrc[u]);
                float4 vv = to_tf32x4(*(const float4*)&vsrc[u]);
                Vs[(dq + u + 0) * AQ + r] = vv.x;
                Vs[(dq + u + 1) * AQ + r] = vv.y;
                Vs[(dq + u + 2) * AQ + r] = vv.z;
                Vs[(dq + u + 3) * AQ + r] = vv.w;
            }
        }
        __syncthreads();

        // --- S = Q K^T via mma ---
        float sf[4][4] = {};
        {
            const uint32_t* Qu = (const uint32_t*)Qs;
            const uint32_t* Ku = (const uint32_t*)Ks;
            #pragma unroll
            for (int ks = 0; ks < 8; ks++) {
                const int kk = ks * 8 + t;
                uint32_t a[4];
                a[0] = Qu[(warpM + g) * AQ + kk];
                a[1] = Qu[(warpM + 8 + g) * AQ + kk];
                a[2] = Qu[(warpM + g) * AQ + kk + 4];
                a[3] = Qu[(warpM + 8 + g) * AQ + kk + 4];
                #pragma unroll
                for (int nt = 0; nt < 4; nt++) {
                    const int cb = warpN + nt * 8 + g;
                    mma_tf32(sf[nt], a, Ku[cb * AQ + kk], Ku[cb * AQ + kk + 4]);
                }
            }
        }
        // mask + scale, write fragments to Ss
        {
            const int gi0 = q0 + warpM + g;
            const int gi1 = gi0 + 8;
            #pragma unroll
            for (int nt = 0; nt < 4; nt++) {
                const int gj = k0b + warpN + nt * 8 + 2 * t;
                const bool m00 = (abs(gi0 - gj)     <= WINDOW) || (gj     < kl);
                const bool m01 = (abs(gi0 - gj - 1) <= WINDOW) || (gj + 1 < kl);
                const bool m10 = (abs(gi1 - gj)     <= WINDOW) || (gj     < kl);
                const bool m11 = (abs(gi1 - gj - 1) <= WINDOW) || (gj + 1 < kl);
                float2 v0 = { m00 ? sf[nt][0] * scale : -1e9f,
                              m01 ? sf[nt][1] * scale : -1e9f };
                float2 v1 = { m10 ? sf[nt][2] * scale : -1e9f,
                              m11 ? sf[nt][3] * scale : -1e9f };
                const int co = warpN + nt * 8 + 2 * t;
                *(float2*)&Ss[(warpM + g)     * SSW + co] = v0;
                *(float2*)&Ss[(warpM + 8 + g) * SSW + co] = v1;
            }
        }
        __syncthreads();

        // --- online softmax: 4 threads per row, 16 cols each ---
        {
            const int qd = tid & 3;
            float* srow = &Ss[r * SSW + qd * 16];
            float mx = -1e30f;
            #pragma unroll
            for (int c = 0; c < 16; c++) mx = fmaxf(mx, srow[c]);
            mx = fmaxf(mx, __shfl_xor_sync(0xffffffffu, mx, 1));
            mx = fmaxf(mx, __shfl_xor_sync(0xffffffffu, mx, 2));
            const float m_old = row_m[r];
            const float m_new = fmaxf(m_old, mx);
            const float corr  = __expf(m_old - m_new);
            float sum = 0.0f;
            #pragma unroll
            for (int c = 0; c < 16; c++) {
                const float p = to_tf32(__expf(srow[c] - m_new));
                srow[c] = p;
                sum += p;
            }
            sum += __shfl_xor_sync(0xffffffffu, sum, 1);
            sum += __shfl_xor_sync(0xffffffffu, sum, 2);
            if (qd == 0) {
                row_l[r] = row_l[r] * corr + sum;
                row_m[r] = m_new;
                row_c[r] = corr;
            }
        }
        __syncthreads();

        // --- O = O*corr + P V via mma ---
        {
            const float c0 = row_c[warpM + g];
            const float c1 = row_c[warpM + 8 + g];
            #pragma unroll
            for (int nt = 0; nt < 4; nt++) {
                o[nt][0] *= c0; o[nt][1] *= c0;
                o[nt][2] *= c1; o[nt][3] *= c1;
            }
            const uint32_t* Pu = (const uint32_t*)Ss;
            const uint32_t* Vu = (const uint32_t*)Vs;
            #pragma unroll
            for (int ks = 0; ks < 8; ks++) {
                const int kk = ks * 8 + t;
                uint32_t a[4];
                a[0] = Pu[(warpM + g) * SSW + kk];
                a[1] = Pu[(warpM + 8 + g) * SSW + kk];
                a[2] = Pu[(warpM + g) * SSW + kk + 4];
                a[3] = Pu[(warpM + 8 + g) * SSW + kk + 4];
                #pragma unroll
                for (int nt = 0; nt < 4; nt++) {
                    const int cb = warpN + nt * 8 + g;
                    mma_tf32(o[nt], a, Vu[cb * AQ + kk], Vu[cb * AQ + kk + 4]);
                }
            }
        }
        __syncthreads();
    }

    // --- normalize + write out ---
    {
        const float i0 = 1.0f / row_l[warpM + g];
        const float i1 = 1.0f / row_l[warpM + 8 + g];
        const int row0 = q0 + warpM + g;
        #pragma unroll
        for (int nt = 0; nt < 4; nt++) {
            const int col = h * DH + warpN + nt * 8 + 2 * t;
            float2 w0 = { o[nt][0] * i0, o[nt][1] * i0 };
            float2 w1 = { o[nt][2] * i1, o[nt][3] * i1 };
            *(float2*)&ao[((size_t)row0 * N_DIM + n) * C_DIM + col] = w0;
            *(float2*)&ao[((size_t)(row0 + 8) * N_DIM + n) * C_DIM + col] = w1;
        }
    }
}

// ---------------------------------------------------------------------------
extern "C" void kernel_launch(void* const* d_in, const int* in_sizes, int n_in,
                              void* d_out, int out_size)
{
    (void)in_sizes; (void)n_in; (void)out_size;
    const float* q  = (const float*)d_in[0];
    const float* k  = (const float*)d_in[1];
    const float* v  = (const float*)d_in[2];
    const float* Wq = (const float*)d_in[3];
    const float* bq = (const float*)d_in[4];
    const float* Wk = (const float*)d_in[5];
    const float* bk = (const float*)d_in[6];
    const float* Wv = (const float*)d_in[7];
    const float* bv = (const float*)d_in[8];
    const float* Wo = (const float*)d_in[9];
    const float* bo = (const float*)d_in[10];
    const int* key_length = (const int*)d_in[11];
    float* out = (float*)d_out;

    float *qp, *kp, *vp, *aop;
    cudaGetSymbolAddress((void**)&qp,  g_qp);
    cudaGetSymbolAddress((void**)&kp,  g_kp);
    cudaGetSymbolAddress((void**)&vp,  g_vp);
    cudaGetSymbolAddress((void**)&aop, g_ao);

    cudaFuncSetAttribute(gemm_tf32_kernel,
                         cudaFuncAttributeMaxDynamicSharedMemorySize, GEMM_SMEM);
    const dim3 gGrid(GN / 128, M_ROWS / 128);  // (8, 32)

    // input projections (tensor-core tf32 mma.sync)
    gemm_tf32_kernel<<<gGrid, 256, GEMM_SMEM>>>(q, Wq, bq, qp);
    gemm_tf32_kernel<<<gGrid, 256, GEMM_SMEM>>>(k, Wk, bk, kp);
    gemm_tf32_kernel<<<gGrid, 256, GEMM_SMEM>>>(v, Wv, bv, vp);

    // attention (tensor-core)
    cudaFuncSetAttribute(attn_kernel,
                         cudaFuncAttributeMaxDynamicSharedMemorySize, ATTN_SMEM);
    attn_kernel<<<dim3(T_DIM / 64, H_DIM, N_DIM), 256, ATTN_SMEM>>>(
        qp, kp, vp, aop, key_length);

    // output projection
    gemm_tf32_kernel<<<gGrid, 256, GEMM_SMEM>>>(aop, Wo, bo, out);
}